// round 4
// baseline (speedup 1.0000x reference)
#include <cuda_runtime.h>
#include <math.h>
#include <float.h>

#define BS 16
#define CH 64
#define NC 81
#define HW 65536          // 256*256
#define FG_STCH 1
#define JCNT (CH - FG_STCH)            // 63
#define SPLIT 4                        // chunks per (b,c) row
#define CHUNK (HW / 4 / SPLIT)         // float4 per chunk = 4096
#define NBLK (BS * CH * SPLIT)         // 4096 blocks
#define NLOSS_BLK 126                  // 8 items/block * 126 = 1008 items
#define WPB 8                          // warps per block

// Scratch (no cudaMalloc allowed)
__device__ float g_maxprob_part[NBLK];
__device__ float g_partial[NLOSS_BLK * 3];
__device__ int   g_count;              // maxprob chunk completions (-> NBLK)
__device__ int   g_loss_count;         // loss block completions   (-> NLOSS_BLK)

// ---------------------------------------------------------------------------
// Fused kernel: every block reduces one 64KB chunk of pred_mask_prob to a
// partial max. The first NLOSS_BLK blocks also own 8 loss items each
// (warp-per-item): the maxprob-independent part (gathers, softmax/CE,
// smooth-L1) is computed BEFORE the streaming phase so its dependent-load
// latency overlaps HBM traffic; only the tiny mp-gather + weighting + global
// reduction happens after a grid-completion spin.
// ---------------------------------------------------------------------------
__global__ __launch_bounds__(256) void fused_kernel(
    const float4* __restrict__ p,            // pred_mask_prob as float4
    const float* __restrict__ cls_logits,    // (bs, ch, C)
    const float* __restrict__ iou_scores,    // (bs, ch, 1)
    const int*   __restrict__ target_ids,    // (bs, ch)
    const int*   __restrict__ map_indices,   // (bs, 2, ch)
    const float* __restrict__ map_ious,      // (bs, ch)
    const float* __restrict__ rand_vals,     // (bs, ch)
    float* __restrict__ out)                 // [iou_loss, cls_loss]
{
    const int blk  = blockIdx.x;
    const int warp = threadIdx.x >> 5;
    const int lane = threadIdx.x & 31;
    const bool loss_block = (blk < NLOSS_BLK);

    // ---------------- loss pre-work (maxprob-independent) ----------------
    int   pj = 0, b = 0;
    float wght_base = 0.0f;   // weight if not removed
    bool  rnd_rm = false;     // rnd < 0.9 part of remove predicate
    float iou_el = 0.0f;      // smooth-L1 element
    float ce = 0.0f;          // cross-entropy element (lane 0 holds it)

    if (loss_block) {
        const int item = blk * WPB + warp;   // 0..1007 exact
        b = item / JCNT;
        const int j = FG_STCH + (item % JCNT);

        pj = map_indices[b * 2 * CH + 0 * CH + j];
        const int gj  = map_indices[b * 2 * CH + 1 * CH + j];
        const int tid = target_ids[b * CH + gj];
        const int cls = max(0, tid - FG_STCH + 1);

        const float iou = map_ious[b * CH + j];
        const float rnd = rand_vals[b * CH + j];
        rnd_rm = (rnd < 0.9f);
        wght_base = (iou < 0.2f) ? 1.0f : 2.0f;

        const float preds_iou = iou_scores[b * CH + pj];
        const float y = fabsf(preds_iou - iou);
        iou_el = (y < 0.1f) ? (y * y * 5.0f) : (y - 0.05f);

        // warp-parallel log-softmax over C=81
        const float* row = cls_logits + (size_t)(b * CH + pj) * NC;
        const float x0 = row[lane];
        const float x1 = row[lane + 32];
        const float x2 = (lane < NC - 64) ? row[lane + 64] : -FLT_MAX;

        float mx = fmaxf(fmaxf(x0, x1), x2);
#pragma unroll
        for (int o = 16; o > 0; o >>= 1)
            mx = fmaxf(mx, __shfl_xor_sync(0xFFFFFFFFu, mx, o));

        float s = expf(x0 - mx) + expf(x1 - mx);
        if (lane < NC - 64) s += expf(x2 - mx);
#pragma unroll
        for (int o = 16; o > 0; o >>= 1)
            s += __shfl_xor_sync(0xFFFFFFFFu, s, o);

        if (lane == 0)
            ce = -(row[cls] - mx - logf(s));   // w[cls] == 1
    }

    // ---------------- streaming maxprob chunk ----------------
    {
        const float4* base = p + (size_t)blk * CHUNK;
        float m0 = -FLT_MAX, m1 = -FLT_MAX, m2 = -FLT_MAX, m3 = -FLT_MAX;
#pragma unroll
        for (int i = 0; i < CHUNK / (256 * 4); i++) {
            const int bi = i * 256 * 4 + threadIdx.x;
            float4 v0 = __ldcs(&base[bi]);
            float4 v1 = __ldcs(&base[bi + 256]);
            float4 v2 = __ldcs(&base[bi + 512]);
            float4 v3 = __ldcs(&base[bi + 768]);
            m0 = fmaxf(m0, fmaxf(fmaxf(v0.x, v0.y), fmaxf(v0.z, v0.w)));
            m1 = fmaxf(m1, fmaxf(fmaxf(v1.x, v1.y), fmaxf(v1.z, v1.w)));
            m2 = fmaxf(m2, fmaxf(fmaxf(v2.x, v2.y), fmaxf(v2.z, v2.w)));
            m3 = fmaxf(m3, fmaxf(fmaxf(v3.x, v3.y), fmaxf(v3.z, v3.w)));
        }
        float m = fmaxf(fmaxf(m0, m1), fmaxf(m2, m3));

#pragma unroll
        for (int o = 16; o > 0; o >>= 1)
            m = fmaxf(m, __shfl_xor_sync(0xFFFFFFFFu, m, o));

        __shared__ float sm[WPB];
        if (lane == 0) sm[warp] = m;
        __syncthreads();
        if (threadIdx.x < WPB) {
            m = sm[threadIdx.x];
#pragma unroll
            for (int o = WPB / 2; o > 0; o >>= 1)
                m = fmaxf(m, __shfl_xor_sync(0xFFu, m, o));
            if (threadIdx.x == 0) {
                g_maxprob_part[blk] = m;
                __threadfence();
                atomicAdd(&g_count, 1);
            }
        }
    }

    if (!loss_block) return;

    // ---------------- wait for all chunks, then finish loss ----------------
    if (threadIdx.x == 0) {
        while (atomicAdd(&g_count, 0) < NBLK) { __nanosleep(64); }
    }
    __syncthreads();

    // mp gather + weight (lane 0 of each warp suffices)
    float v0 = 0.0f, v1 = 0.0f, v2 = 0.0f;
    if (lane == 0) {
        const float* mpp = &g_maxprob_part[(b * CH + pj) * SPLIT];
        const float mp = fmaxf(fmaxf(mpp[0], mpp[1]), fmaxf(mpp[2], mpp[3]));
        const bool remove = (mp < 0.1f) && rnd_rm;
        const float wght = remove ? 0.0f : wght_base;
        v0 = wght;
        v1 = iou_el * wght;
        v2 = ce * wght;
    }

    // block reduce across 8 warps
    __shared__ float s0[WPB], s1[WPB], s2[WPB];
    if (lane == 0) { s0[warp] = v0; s1[warp] = v1; s2[warp] = v2; }
    __syncthreads();

    __shared__ bool is_last;
    if (warp == 0) {
        float a0 = (lane < WPB) ? s0[lane] : 0.0f;
        float a1 = (lane < WPB) ? s1[lane] : 0.0f;
        float a2 = (lane < WPB) ? s2[lane] : 0.0f;
#pragma unroll
        for (int o = WPB / 2; o > 0; o >>= 1) {
            a0 += __shfl_xor_sync(0xFFFFFFFFu, a0, o);
            a1 += __shfl_xor_sync(0xFFFFFFFFu, a1, o);
            a2 += __shfl_xor_sync(0xFFFFFFFFu, a2, o);
        }
        if (lane == 0) {
            g_partial[blk * 3 + 0] = a0;
            g_partial[blk * 3 + 1] = a1;
            g_partial[blk * 3 + 2] = a2;
            __threadfence();
            const int prev = atomicAdd(&g_loss_count, 1);
            is_last = (prev == NLOSS_BLK - 1);
        }
        __syncwarp();

        // final reduction over the 126 fixed partial slots (deterministic)
        if (is_last) {
            float b0 = 0.0f, b1 = 0.0f, b2 = 0.0f;
#pragma unroll
            for (int k = 0; k < 4; k++) {
                const int i = lane + 32 * k;
                if (i < NLOSS_BLK) {
                    b0 += g_partial[i * 3 + 0];
                    b1 += g_partial[i * 3 + 1];
                    b2 += g_partial[i * 3 + 2];
                }
            }
#pragma unroll
            for (int o = 16; o > 0; o >>= 1) {
                b0 += __shfl_xor_sync(0xFFFFFFFFu, b0, o);
                b1 += __shfl_xor_sync(0xFFFFFFFFu, b1, o);
                b2 += __shfl_xor_sync(0xFFFFFFFFu, b2, o);
            }
            if (lane == 0) {
                const float wsum = b0 + 0.0001f;
                out[0] = b1 / wsum;   // iou_loss
                out[1] = b2 / wsum;   // cls_loss
                g_count = 0;          // reset for next graph replay
                g_loss_count = 0;
            }
        }
    }
}

// ---------------------------------------------------------------------------
extern "C" void kernel_launch(void* const* d_in, const int* in_sizes, int n_in,
                              void* d_out, int out_size) {
    const float* cls_logits     = (const float*)d_in[0];
    const float* iou_scores     = (const float*)d_in[1];
    const int*   target_ids     = (const int*)  d_in[2];
    const int*   map_indices    = (const int*)  d_in[3];
    const float* map_ious       = (const float*)d_in[4];
    const float* pred_mask_prob = (const float*)d_in[5];
    const float* rand_vals      = (const float*)d_in[6];
    float* out = (float*)d_out;

    fused_kernel<<<NBLK, 256>>>((const float4*)pred_mask_prob,
                                cls_logits, iou_scores, target_ids,
                                map_indices, map_ious, rand_vals, out);
}

// round 5
// speedup vs baseline: 1.0201x; 1.0201x over previous
#include <cuda_runtime.h>
#include <math.h>
#include <float.h>

#define BS 16
#define CH 64
#define NC 81
#define HW 65536          // 256*256
#define FG_STCH 1
#define JCNT (CH - FG_STCH)            // 63
#define SPLIT 4                        // chunks per (b,c) row
#define CHUNK (HW / 4 / SPLIT)         // float4 per chunk = 4096
#define NBLK (BS * CH * SPLIT)         // 4096 blocks
#define NLOSS_BLK 126                  // 8 items/block * 126 = 1008 items
#define WPB 8                          // warps per block

// Scratch (no cudaMalloc allowed)
__device__ float g_maxprob_part[NBLK];
__device__ float g_partial[NLOSS_BLK * 3];
__device__ int   g_count;              // maxprob chunk completions (-> NBLK)
__device__ int   g_loss_count;         // loss block completions   (-> NLOSS_BLK)

// ---------------------------------------------------------------------------
// Fused kernel, phase order fixed vs R4:
//   phase 1 (all blocks): stream one 64KB chunk -> partial max. Starts
//           immediately so DRAM saturates from the first cycle.
//   phase 2 (blocks 0..125 only, wave-1 residents): maxprob-independent loss
//           pre-work (gathers, softmax/CE, smooth-L1) — overlapped with the
//           remaining streaming waves of the other 3970 blocks.
//   phase 3: spin until all chunks done, gather mp, weight, reduce; the last
//           loss block finalizes the two outputs and resets counters.
// ---------------------------------------------------------------------------
__global__ __launch_bounds__(256) void fused_kernel(
    const float4* __restrict__ p,            // pred_mask_prob as float4
    const float* __restrict__ cls_logits,    // (bs, ch, C)
    const float* __restrict__ iou_scores,    // (bs, ch, 1)
    const int*   __restrict__ target_ids,    // (bs, ch)
    const int*   __restrict__ map_indices,   // (bs, 2, ch)
    const float* __restrict__ map_ious,      // (bs, ch)
    const float* __restrict__ rand_vals,     // (bs, ch)
    float* __restrict__ out)                 // [iou_loss, cls_loss]
{
    const int blk  = blockIdx.x;
    const int warp = threadIdx.x >> 5;
    const int lane = threadIdx.x & 31;
    const bool loss_block = (blk < NLOSS_BLK);

    // ---------------- phase 1: streaming maxprob chunk ----------------
    {
        const float4* base = p + (size_t)blk * CHUNK;
        float m0 = -FLT_MAX, m1 = -FLT_MAX, m2 = -FLT_MAX, m3 = -FLT_MAX;
#pragma unroll
        for (int i = 0; i < CHUNK / (256 * 4); i++) {
            const int bi = i * 256 * 4 + threadIdx.x;
            float4 v0 = __ldcs(&base[bi]);
            float4 v1 = __ldcs(&base[bi + 256]);
            float4 v2 = __ldcs(&base[bi + 512]);
            float4 v3 = __ldcs(&base[bi + 768]);
            m0 = fmaxf(m0, fmaxf(fmaxf(v0.x, v0.y), fmaxf(v0.z, v0.w)));
            m1 = fmaxf(m1, fmaxf(fmaxf(v1.x, v1.y), fmaxf(v1.z, v1.w)));
            m2 = fmaxf(m2, fmaxf(fmaxf(v2.x, v2.y), fmaxf(v2.z, v2.w)));
            m3 = fmaxf(m3, fmaxf(fmaxf(v3.x, v3.y), fmaxf(v3.z, v3.w)));
        }
        float m = fmaxf(fmaxf(m0, m1), fmaxf(m2, m3));

#pragma unroll
        for (int o = 16; o > 0; o >>= 1)
            m = fmaxf(m, __shfl_xor_sync(0xFFFFFFFFu, m, o));

        __shared__ float sm[WPB];
        if (lane == 0) sm[warp] = m;
        __syncthreads();
        if (threadIdx.x < WPB) {
            m = sm[threadIdx.x];
#pragma unroll
            for (int o = WPB / 2; o > 0; o >>= 1)
                m = fmaxf(m, __shfl_xor_sync(0xFFu, m, o));
            if (threadIdx.x == 0) {
                g_maxprob_part[blk] = m;
                __threadfence();
                atomicAdd(&g_count, 1);
            }
        }
    }

    if (!loss_block) return;

    // ---------------- phase 2: loss pre-work (maxprob-independent) ----------
    // One warp per item; overlapped with remaining streaming waves.
    const int item = blk * WPB + warp;       // 0..1007 exact
    const int b = item / JCNT;
    const int j = FG_STCH + (item % JCNT);

    const int pj  = map_indices[b * 2 * CH + 0 * CH + j];
    const int gj  = map_indices[b * 2 * CH + 1 * CH + j];
    const int tid = target_ids[b * CH + gj];
    const int cls = max(0, tid - FG_STCH + 1);

    const float iou = map_ious[b * CH + j];
    const float rnd = rand_vals[b * CH + j];
    const bool  rnd_rm = (rnd < 0.9f);
    const float wght_base = (iou < 0.2f) ? 1.0f : 2.0f;

    const float preds_iou = iou_scores[b * CH + pj];
    const float y = fabsf(preds_iou - iou);
    const float iou_el = (y < 0.1f) ? (y * y * 5.0f) : (y - 0.05f);

    // warp-parallel log-softmax over C=81
    const float* row = cls_logits + (size_t)(b * CH + pj) * NC;
    const float x0 = row[lane];
    const float x1 = row[lane + 32];
    const float x2 = (lane < NC - 64) ? row[lane + 64] : -FLT_MAX;

    float mx = fmaxf(fmaxf(x0, x1), x2);
#pragma unroll
    for (int o = 16; o > 0; o >>= 1)
        mx = fmaxf(mx, __shfl_xor_sync(0xFFFFFFFFu, mx, o));

    float s = expf(x0 - mx) + expf(x1 - mx);
    if (lane < NC - 64) s += expf(x2 - mx);
#pragma unroll
    for (int o = 16; o > 0; o >>= 1)
        s += __shfl_xor_sync(0xFFFFFFFFu, s, o);

    float ce = 0.0f;
    if (lane == 0)
        ce = -(row[cls] - mx - logf(s));     // w[cls] == 1

    // ---------------- phase 3: wait for all chunks, finish loss -------------
    if (threadIdx.x == 0) {
        while (atomicAdd(&g_count, 0) < NBLK) { __nanosleep(128); }
    }
    __syncthreads();
    __threadfence();   // order g_maxprob_part reads after the counter observation

    float v0 = 0.0f, v1 = 0.0f, v2 = 0.0f;
    if (lane == 0) {
        const float* mpp = &g_maxprob_part[(b * CH + pj) * SPLIT];
        const float mp = fmaxf(fmaxf(mpp[0], mpp[1]), fmaxf(mpp[2], mpp[3]));
        const bool remove = (mp < 0.1f) && rnd_rm;
        const float wght = remove ? 0.0f : wght_base;
        v0 = wght;
        v1 = iou_el * wght;
        v2 = ce * wght;
    }

    // block reduce across 8 warps
    __shared__ float s0[WPB], s1[WPB], s2[WPB];
    if (lane == 0) { s0[warp] = v0; s1[warp] = v1; s2[warp] = v2; }
    __syncthreads();

    __shared__ bool is_last;
    if (warp == 0) {
        float a0 = (lane < WPB) ? s0[lane] : 0.0f;
        float a1 = (lane < WPB) ? s1[lane] : 0.0f;
        float a2 = (lane < WPB) ? s2[lane] : 0.0f;
#pragma unroll
        for (int o = WPB / 2; o > 0; o >>= 1) {
            a0 += __shfl_xor_sync(0xFFFFFFFFu, a0, o);
            a1 += __shfl_xor_sync(0xFFFFFFFFu, a1, o);
            a2 += __shfl_xor_sync(0xFFFFFFFFu, a2, o);
        }
        if (lane == 0) {
            g_partial[blk * 3 + 0] = a0;
            g_partial[blk * 3 + 1] = a1;
            g_partial[blk * 3 + 2] = a2;
            __threadfence();
            const int prev = atomicAdd(&g_loss_count, 1);
            is_last = (prev == NLOSS_BLK - 1);
        }
        __syncwarp();

        // last loss block: deterministic fixed-order final reduction
        if (is_last) {
            float b0 = 0.0f, b1 = 0.0f, b2 = 0.0f;
#pragma unroll
            for (int k = 0; k < 4; k++) {
                const int i = lane + 32 * k;
                if (i < NLOSS_BLK) {
                    b0 += g_partial[i * 3 + 0];
                    b1 += g_partial[i * 3 + 1];
                    b2 += g_partial[i * 3 + 2];
                }
            }
#pragma unroll
            for (int o = 16; o > 0; o >>= 1) {
                b0 += __shfl_xor_sync(0xFFFFFFFFu, b0, o);
                b1 += __shfl_xor_sync(0xFFFFFFFFu, b1, o);
                b2 += __shfl_xor_sync(0xFFFFFFFFu, b2, o);
            }
            if (lane == 0) {
                const float wsum = b0 + 0.0001f;
                out[0] = b1 / wsum;   // iou_loss
                out[1] = b2 / wsum;   // cls_loss
                g_count = 0;          // reset for next graph replay
                g_loss_count = 0;
            }
        }
    }
}

// ---------------------------------------------------------------------------
extern "C" void kernel_launch(void* const* d_in, const int* in_sizes, int n_in,
                              void* d_out, int out_size) {
    const float* cls_logits     = (const float*)d_in[0];
    const float* iou_scores     = (const float*)d_in[1];
    const int*   target_ids     = (const int*)  d_in[2];
    const int*   map_indices    = (const int*)  d_in[3];
    const float* map_ious       = (const float*)d_in[4];
    const float* pred_mask_prob = (const float*)d_in[5];
    const float* rand_vals      = (const float*)d_in[6];
    float* out = (float*)d_out;

    fused_kernel<<<NBLK, 256>>>((const float4*)pred_mask_prob,
                                cls_logits, iou_scores, target_ids,
                                map_indices, map_ious, rand_vals, out);
}